// round 12
// baseline (speedup 1.0000x reference)
#include <cuda_runtime.h>

// Grouped shifted conv1d:
//   t = roll(x, +1, axis=3); patches = unfold(t, k=3, pad=1) along last axis
//   y[o,k,n,m] = sum_{i,j} patches[o*64+i, n, j, m] * W[i,k,j]
//   out = roll(y, +1, axis=2)  (H roll folded into store index)
//
// Grid: (56 rows, 2 groups) = 112 CTAs, single wave. Block: 896 = 14mq x 4kq x 16iq.
// Thread: 4m x 4k register tile over 4 input channels.
// Dynamic smem (85 KB) so xs/ws/red coexist -> only TWO barriers:
//   stage -> bar -> compute + write own slab -> bar -> 16-way reduce + store.

#define NT 896
#define XPITCH 60   // floats; i*60 is 16B-aligned so float4 row loads work

// dynamic smem layout (floats):
//   xs : [0, 3840)        xs[i][u], 64 x 60, rolled + zero-padded
//   ws : [3840, 6912)     ws[j][i][k], k contiguous
//   red: [6912, 21248)    red[iq][k][m], 16 x 16 x 56
#define XS_OFF  0
#define WS_OFF  3840
#define RED_OFF 6912
#define SMEM_FLOATS (RED_OFF + 16 * 16 * 56)

__global__ void __launch_bounds__(NT)
shiftconv_kernel(const float* __restrict__ x,
                 const float* __restrict__ W,
                 float* __restrict__ out)
{
    extern __shared__ float sm[];
    float* xs  = sm + XS_OFF;
    float* ws  = sm + WS_OFF;
    float* red = sm + RED_OFF;

    const int n = blockIdx.x;   // input H row 0..55
    const int o = blockIdx.y;   // channel group 0..1

    const int tid = threadIdx.x;
    const int mq  = tid % 14;          // 4-wide m tile index
    const int kq  = (tid / 14) % 4;    // 4-wide k tile index
    const int iq  = tid / 56;          // 0..15, 4-channel slice

    // zero pad columns u=0 and u=57
    if (tid < 128)
        xs[(tid >> 1) * XPITCH + (tid & 1) * 57] = 0.0f;

    // --- stage x: 4 LDGs in flight per thread (896*4 = 64*56), fused roll ---
    // 896 = 16*56: u constant per thread, i steps by 16 -> coalesced over m.
    {
        const float* xg  = x + (o * 64) * 3136 + n * 56;
        const int    u   = tid % 56 + 1;          // 1..56
        const int    src = (tid % 56 + 55) % 56;  // (u-2) mod 56
        const int    i0  = tid / 56;              // 0..15
        #pragma unroll
        for (int s = 0; s < 4; ++s) {
            const int i = i0 + 16 * s;
            xs[i * XPITCH + u] = xg[i * 3136 + src];
        }
    }

    // --- stage W: src (i,k,j) row-major -> ws[j*1024 + i*16 + k] ---
    #pragma unroll
    for (int s = 0; s < 4; ++s) {
        const int t = tid + s * NT;
        if (t < 3072) {
            const int k = t & 15;
            const int i = (t >> 4) & 63;
            const int j = t >> 10;
            ws[t] = W[i * 48 + k * 3 + j];
        }
    }
    __syncthreads();                    // barrier 1: staging visible

    // --- compute: 4m x 4k register tile, i in [iq*4, iq*4+4) ---
    const int mbase = mq * 4;
    const int kbase = kq * 4;
    float acc[4][4];                    // [kk][d]
    #pragma unroll
    for (int a = 0; a < 4; ++a)
        #pragma unroll
        for (int b = 0; b < 4; ++b) acc[a][b] = 0.f;

    const float* xrow = xs + iq * 4 * XPITCH + mbase;
    const float* wrow = ws + iq * 4 * 16 + kbase;

    #pragma unroll
    for (int ii = 0; ii < 4; ++ii) {
        // 6 x taps serve outputs mbase..mbase+3 (taps m..m+5 in padded coords)
        const float4 xlo = *reinterpret_cast<const float4*>(xrow + ii * XPITCH);
        const float2 xhi = *reinterpret_cast<const float2*>(xrow + ii * XPITCH + 4);
        const float xv[6] = { xlo.x, xlo.y, xlo.z, xlo.w, xhi.x, xhi.y };

        const float4 w0 = *reinterpret_cast<const float4*>(wrow + ii * 16);          // j=0
        const float4 w1 = *reinterpret_cast<const float4*>(wrow + ii * 16 + 1024);   // j=1
        const float4 w2 = *reinterpret_cast<const float4*>(wrow + ii * 16 + 2048);   // j=2
        const float wj[3][4] = { {w0.x,w0.y,w0.z,w0.w},
                                 {w1.x,w1.y,w1.z,w1.w},
                                 {w2.x,w2.y,w2.z,w2.w} };

        #pragma unroll
        for (int kk = 0; kk < 4; ++kk)
            #pragma unroll
            for (int d = 0; d < 4; ++d)
                acc[kk][d] += xv[d] * wj[0][kk]
                            + xv[d + 1] * wj[1][kk]
                            + xv[d + 2] * wj[2][kk];
    }

    // --- write own slab immediately (distinct smem region -> no guard barrier) ---
    #pragma unroll
    for (int kk = 0; kk < 4; ++kk)
        *reinterpret_cast<float4*>(
            red + (iq * 16 + kbase + kk) * 56 + mbase) =
            make_float4(acc[kk][0], acc[kk][1], acc[kk][2], acc[kk][3]);
    __syncthreads();                    // barrier 2: all partials visible

    // --- final: 896 threads = 16 k x 56 m; 16-way sum + rolled store ---
    {
        const int k = tid / 56;
        const int m = tid % 56;
        float s0 = 0.f, s1 = 0.f;       // two chains to halve dependent-add latency
        #pragma unroll
        for (int q = 0; q < 8; ++q) {
            s0 += red[((2 * q    ) * 16 + k) * 56 + m];
            s1 += red[((2 * q + 1) * 16 + k) * 56 + m];
        }
        const int n_out = (n + 1) % 56;
        out[((o * 16 + k) * 56 + n_out) * 56 + m] = s0 + s1;
    }
}

extern "C" void kernel_launch(void* const* d_in, const int* in_sizes, int n_in,
                              void* d_out, int out_size)
{
    const float* x = (const float*)d_in[0];   // (1,128,56,56) fp32
    const float* W = (const float*)d_in[1];   // (64,16,3) fp32
    float* out     = (float*)d_out;           // (1,32,56,56) fp32

    const int smem_bytes = SMEM_FLOATS * sizeof(float);   // ~85 KB
    cudaFuncSetAttribute(shiftconv_kernel,
                         cudaFuncAttributeMaxDynamicSharedMemorySize, smem_bytes);

    dim3 grid(56, 2);
    shiftconv_kernel<<<grid, NT, smem_bytes>>>(x, W, out);
}

// round 14
// speedup vs baseline: 1.0895x; 1.0895x over previous
#include <cuda_runtime.h>

// Grouped shifted conv1d:
//   t = roll(x, +1, axis=3); patches = unfold(t, k=3, pad=1) along last axis
//   y[o,k,n,m] = sum_{i,j} patches[o*64+i, n, j, m] * W[i,k,j]
//   out = roll(y, +1, axis=2)  (H roll folded into store index)
//
// Grid: (56 rows, 2 groups) = 112 CTAs, single wave. Block: 448 = 14mq x 4kq x 8iq.
// Thread: 4m x 4k register tile, 8 channels total (4 per pipeline stage).
// Two-stage cp.async pipeline: compute channels 0..31 while 32..63 stream in.

#define NT 448
#define XPITCH 60   // floats; i*60 is 16B-aligned so float4 row loads work

// dynamic smem layout (floats):
//   xs : [0, 3840)        xs[i][u], 64 x 60, rolled + zero-padded
//   ws : [3840, 6912)     ws[j][i][k], k contiguous
//   red: [6912, 14080)    red[iq][k][m], 8 x 16 x 56
#define XS_OFF  0
#define WS_OFF  3840
#define RED_OFF 6912
#define SMEM_FLOATS (RED_OFF + 8 * 16 * 56)

#define CP_ASYNC4(dst, src) \
    asm volatile("cp.async.ca.shared.global [%0], [%1], 4;" \
                 :: "r"(dst), "l"(src) : "memory")
#define CP_COMMIT()  asm volatile("cp.async.commit_group;" ::: "memory")
#define CP_WAIT(N)   asm volatile("cp.async.wait_group %0;" :: "n"(N) : "memory")

__global__ void __launch_bounds__(NT)
shiftconv_kernel(const float* __restrict__ x,
                 const float* __restrict__ W,
                 float* __restrict__ out)
{
    extern __shared__ float sm[];
    float* xs  = sm + XS_OFF;
    float* ws  = sm + WS_OFF;
    float* red = sm + RED_OFF;

    const unsigned xs_u32 = (unsigned)__cvta_generic_to_shared(xs);
    const unsigned ws_u32 = (unsigned)__cvta_generic_to_shared(ws);

    const int n = blockIdx.x;   // input H row 0..55
    const int o = blockIdx.y;   // channel group 0..1

    const int tid = threadIdx.x;
    const int mq  = tid % 14;          // 4-wide m tile index
    const int kq  = (tid / 14) % 4;    // 4-wide k tile index
    const int iq  = tid / 56;          // 0..7 channel slice (per stage)

    // zero pad columns u=0 and u=57 (plain stores, covered by barrier 1)
    if (tid < 128)
        xs[(tid >> 1) * XPITCH + (tid & 1) * 57] = 0.0f;

    const float* xg  = x + (o * 64) * 3136 + n * 56;
    const int    u   = tid % 56 + 1;          // 1..56
    const int    src = (tid % 56 + 55) % 56;  // fused +1 circular roll
    const int    i0  = tid / 56;              // 0..7

    // --- group 0: x channels 0..31  +  W ---
    #pragma unroll
    for (int s = 0; s < 4; ++s) {
        const int i = i0 + 8 * s;
        CP_ASYNC4(xs_u32 + (i * XPITCH + u) * 4, xg + i * 3136 + src);
    }
    // W: src (i,k,j) row-major -> ws[j*1024 + i*16 + k]
    #pragma unroll
    for (int s = 0; s < 7; ++s) {
        const int t = tid + s * NT;
        if (t < 3072) {
            const int k = t & 15;
            const int i = (t >> 4) & 63;
            const int j = t >> 10;
            CP_ASYNC4(ws_u32 + t * 4, W + i * 48 + k * 3 + j);
        }
    }
    CP_COMMIT();

    // --- group 1: x channels 32..63 ---
    #pragma unroll
    for (int s = 0; s < 4; ++s) {
        const int i = 32 + i0 + 8 * s;
        CP_ASYNC4(xs_u32 + (i * XPITCH + u) * 4, xg + i * 3136 + src);
    }
    CP_COMMIT();

    const int mbase = mq * 4;
    const int kbase = kq * 4;
    float acc[4][4];
    #pragma unroll
    for (int a = 0; a < 4; ++a)
        #pragma unroll
        for (int b = 0; b < 4; ++b) acc[a][b] = 0.f;

    // --- stage A: wait group 0, compute channels [iq*4, iq*4+4) ---
    CP_WAIT(1);
    __syncthreads();                    // group-0 data visible block-wide

    #pragma unroll
    for (int half = 0; half < 2; ++half) {
        if (half == 1) {                // stage B: channels 32+
            CP_WAIT(0);
            __syncthreads();            // group-1 data visible block-wide
        }
        const int cb = half * 32 + iq * 4;
        const float* xrow = xs + cb * XPITCH + mbase;
        const float* wrow = ws + cb * 16 + kbase;

        #pragma unroll
        for (int ii = 0; ii < 4; ++ii) {
            // 6 x taps serve outputs mbase..mbase+3 (taps m..m+5 padded)
            const float4 xlo = *reinterpret_cast<const float4*>(xrow + ii * XPITCH);
            const float2 xhi = *reinterpret_cast<const float2*>(xrow + ii * XPITCH + 4);
            const float xv[6] = { xlo.x, xlo.y, xlo.z, xlo.w, xhi.x, xhi.y };

            const float4 w0 = *reinterpret_cast<const float4*>(wrow + ii * 16);          // j=0
            const float4 w1 = *reinterpret_cast<const float4*>(wrow + ii * 16 + 1024);   // j=1
            const float4 w2 = *reinterpret_cast<const float4*>(wrow + ii * 16 + 2048);   // j=2
            const float wj[3][4] = { {w0.x,w0.y,w0.z,w0.w},
                                     {w1.x,w1.y,w1.z,w1.w},
                                     {w2.x,w2.y,w2.z,w2.w} };

            #pragma unroll
            for (int kk = 0; kk < 4; ++kk)
                #pragma unroll
                for (int d = 0; d < 4; ++d)
                    acc[kk][d] += xv[d] * wj[0][kk]
                                + xv[d + 1] * wj[1][kk]
                                + xv[d + 2] * wj[2][kk];
        }
    }

    // --- write own slab (distinct smem region) ---
    #pragma unroll
    for (int kk = 0; kk < 4; ++kk)
        *reinterpret_cast<float4*>(
            red + (iq * 16 + kbase + kk) * 56 + mbase) =
            make_float4(acc[kk][0], acc[kk][1], acc[kk][2], acc[kk][3]);
    __syncthreads();                    // all partials visible

    // --- final: 448 threads = 16 k x 28 m-pairs; 8-way sum + rolled store ---
    {
        const int k  = tid / 28;
        const int mp = (tid % 28) * 2;
        float2 s0 = make_float2(0.f, 0.f), s1 = make_float2(0.f, 0.f);
        #pragma unroll
        for (int q = 0; q < 4; ++q) {
            const float2 p0 = *reinterpret_cast<const float2*>(
                red + ((2 * q    ) * 16 + k) * 56 + mp);
            const float2 p1 = *reinterpret_cast<const float2*>(
                red + ((2 * q + 1) * 16 + k) * 56 + mp);
            s0.x += p0.x; s0.y += p0.y;
            s1.x += p1.x; s1.y += p1.y;
        }
        const int n_out = (n + 1) % 56;
        *reinterpret_cast<float2*>(
            out + ((o * 16 + k) * 56 + n_out) * 56 + mp) =
            make_float2(s0.x + s1.x, s0.y + s1.y);
    }
}

extern "C" void kernel_launch(void* const* d_in, const int* in_sizes, int n_in,
                              void* d_out, int out_size)
{
    const float* x = (const float*)d_in[0];   // (1,128,56,56) fp32
    const float* W = (const float*)d_in[1];   // (64,16,3) fp32
    float* out     = (float*)d_out;           // (1,32,56,56) fp32

    const int smem_bytes = SMEM_FLOATS * sizeof(float);   // ~55 KB
    cudaFuncSetAttribute(shiftconv_kernel,
                         cudaFuncAttributeMaxDynamicSharedMemorySize, smem_bytes);

    dim3 grid(56, 2);
    shiftconv_kernel<<<grid, NT, smem_bytes>>>(x, W, out);
}

// round 15
// speedup vs baseline: 1.3527x; 1.2415x over previous
#include <cuda_runtime.h>

// Grouped shifted conv1d:
//   t = roll(x, +1, axis=3); patches = unfold(t, k=3, pad=1) along last axis
//   y[o,k,n,m] = sum_{i,j} patches[o*64+i, n, j, m] * W[i,k,j]
//   out = roll(y, +1, axis=2)  (H roll folded into store index)
//
// Grid: (56 rows, 2 groups) = 112 CTAs, single wave. Block: 896 = 14mq x 4kq x 16iq.
// Thread: 4m x 4k tile over 4 channels, computed with packed fma.rn.f32x2:
// W's [j][i][k] layout gives k-pairs as free b64 operands (LDS.128 reinterpret),
// only the 6 x-tap {a,a} dups cost a mov. 24 FFMA2 + 6 mov vs 48 FFMA per channel.

#define NT 896
#define XPITCH 60   // floats; i*60 is 16B-aligned so float4 row loads work

// dynamic smem layout (floats):
//   xs : [0, 3840)        xs[i][u], 64 x 60, rolled + zero-padded
//   ws : [3840, 6912)     ws[j][i][k], k contiguous
//   red: [6912, 21248)    red[iq][k][m], 16 x 16 x 56
#define XS_OFF  0
#define WS_OFF  3840
#define RED_OFF 6912
#define SMEM_FLOATS (RED_OFF + 16 * 16 * 56)

__global__ void __launch_bounds__(NT)
shiftconv_kernel(const float* __restrict__ x,
                 const float* __restrict__ W,
                 float* __restrict__ out)
{
    extern __shared__ float sm[];
    float* xs  = sm + XS_OFF;
    float* ws  = sm + WS_OFF;
    float* red = sm + RED_OFF;

    const int n = blockIdx.x;   // input H row 0..55
    const int o = blockIdx.y;   // channel group 0..1

    const int tid = threadIdx.x;
    const int mq  = tid % 14;          // 4-wide m tile index
    const int kq  = (tid / 14) % 4;    // 4-wide k tile index
    const int iq  = tid / 56;          // 0..15, 4-channel slice

    // zero pad columns u=0 and u=57
    if (tid < 128)
        xs[(tid >> 1) * XPITCH + (tid & 1) * 57] = 0.0f;

    // --- stage x: 4 LDGs in flight per thread (896*4 = 64*56), fused roll ---
    {
        const float* xg  = x + (o * 64) * 3136 + n * 56;
        const int    u   = tid % 56 + 1;          // 1..56
        const int    src = (tid % 56 + 55) % 56;  // (u-2) mod 56
        const int    i0  = tid / 56;              // 0..15
        #pragma unroll
        for (int s = 0; s < 4; ++s) {
            const int i = i0 + 16 * s;
            xs[i * XPITCH + u] = xg[i * 3136 + src];
        }
    }

    // --- stage W: src (i,k,j) row-major -> ws[j*1024 + i*16 + k] ---
    #pragma unroll
    for (int s = 0; s < 4; ++s) {
        const int t = tid + s * NT;
        if (t < 3072) {
            const int k = t & 15;
            const int i = (t >> 4) & 63;
            const int j = t >> 10;
            ws[t] = W[i * 48 + k * 3 + j];
        }
    }
    __syncthreads();                    // barrier 1: staging visible

    // --- compute: 4m x 4k tile via f32x2, i in [iq*4, iq*4+4) ---
    const int mbase = mq * 4;
    const int kbase = kq * 4;

    // packed accumulators: accP0[d] = {k0,k1} results, accP1[d] = {k2,k3}
    unsigned long long accP0[4] = {0ull, 0ull, 0ull, 0ull};
    unsigned long long accP1[4] = {0ull, 0ull, 0ull, 0ull};

    const float* xrow = xs + iq * 4 * XPITCH + mbase;
    const float* wrow = ws + iq * 4 * 16 + kbase;

    #pragma unroll
    for (int ii = 0; ii < 4; ++ii) {
        // 6 x taps serve outputs mbase..mbase+3 (taps m..m+5 in padded coords)
        const float4 xlo = *reinterpret_cast<const float4*>(xrow + ii * XPITCH);
        const float2 xhi = *reinterpret_cast<const float2*>(xrow + ii * XPITCH + 4);
        const float xv[6] = { xlo.x, xlo.y, xlo.z, xlo.w, xhi.x, xhi.y };

        // W k-quad as two packed b64 pairs, directly from LDS.128 (no movs)
        const ulonglong2 wj0 = *reinterpret_cast<const ulonglong2*>(wrow + ii * 16);          // j=0
        const ulonglong2 wj1 = *reinterpret_cast<const ulonglong2*>(wrow + ii * 16 + 1024);   // j=1
        const ulonglong2 wj2 = *reinterpret_cast<const ulonglong2*>(wrow + ii * 16 + 2048);   // j=2
        const unsigned long long wlo[3] = { wj0.x, wj1.x, wj2.x };   // {k0,k1}
        const unsigned long long whi[3] = { wj0.y, wj1.y, wj2.y };   // {k2,k3}

        unsigned long long xd[6];
        #pragma unroll
        for (int t = 0; t < 6; ++t)
            asm("mov.b64 %0, {%1, %1};" : "=l"(xd[t]) : "f"(xv[t]));

        #pragma unroll
        for (int d = 0; d < 4; ++d)
            #pragma unroll
            for (int j = 0; j < 3; ++j) {
                asm("fma.rn.f32x2 %0, %1, %2, %0;"
                    : "+l"(accP0[d]) : "l"(xd[d + j]), "l"(wlo[j]));
                asm("fma.rn.f32x2 %0, %1, %2, %0;"
                    : "+l"(accP1[d]) : "l"(xd[d + j]), "l"(whi[j]));
            }
    }

    // unpack: acc[kk][d]
    float acc[4][4];
    #pragma unroll
    for (int d = 0; d < 4; ++d) {
        asm("mov.b64 {%0, %1}, %2;" : "=f"(acc[0][d]), "=f"(acc[1][d]) : "l"(accP0[d]));
        asm("mov.b64 {%0, %1}, %2;" : "=f"(acc[2][d]), "=f"(acc[3][d]) : "l"(accP1[d]));
    }

    // --- write own slab (distinct smem region -> no guard barrier) ---
    #pragma unroll
    for (int kk = 0; kk < 4; ++kk)
        *reinterpret_cast<float4*>(
            red + (iq * 16 + kbase + kk) * 56 + mbase) =
            make_float4(acc[kk][0], acc[kk][1], acc[kk][2], acc[kk][3]);
    __syncthreads();                    // barrier 2: all partials visible

    // --- final: 896 threads = 16 k x 56 m; 16-way sum + rolled store ---
    {
        const int k = tid / 56;
        const int m = tid % 56;
        float s0 = 0.f, s1 = 0.f;       // two chains to halve dependent-add latency
        #pragma unroll
        for (int q = 0; q < 8; ++q) {
            s0 += red[((2 * q    ) * 16 + k) * 56 + m];
            s1 += red[((2 * q + 1) * 16 + k) * 56 + m];
        }
        const int n_out = (n + 1) % 56;
        out[((o * 16 + k) * 56 + n_out) * 56 + m] = s0 + s1;
    }
}

extern "C" void kernel_launch(void* const* d_in, const int* in_sizes, int n_in,
                              void* d_out, int out_size)
{
    const float* x = (const float*)d_in[0];   // (1,128,56,56) fp32
    const float* W = (const float*)d_in[1];   // (64,16,3) fp32
    float* out     = (float*)d_out;           // (1,32,56,56) fp32

    const int smem_bytes = SMEM_FLOATS * sizeof(float);   // ~85 KB
    cudaFuncSetAttribute(shiftconv_kernel,
                         cudaFuncAttributeMaxDynamicSharedMemorySize, smem_bytes);

    dim3 grid(56, 2);
    shiftconv_kernel<<<grid, NT, smem_bytes>>>(x, W, out);
}